// round 1
// baseline (speedup 1.0000x reference)
#include <cuda_runtime.h>

// Problem constants
#define NB   8          // batch
#define NC   256        // channels
#define NM   128        // m = C/2
#define NPIX 16384      // N = H*W
#define EPSV 1e-6f

// ---------------- scratch (static device arrays; no allocation) ----------------
__device__ float g_QKV[(size_t)NB * 512 * NPIX];   // rows 0-127 Q, 128-255 K, 256-511 V
__device__ float g_invQ[NB * NPIX];
__device__ float g_invK[NB * NPIX];
__device__ float g_Ksum[NB * NM];
__device__ float g_vsum[NB * NC];
__device__ float g_matrix[NB * NM * NC];           // [b][m][C]
__device__ float g_tailor[NB * NPIX];

// ---------------- zero accumulators (graph-replay determinism) ----------------
__global__ void zero_kernel() {
    const int total = NB*NM + NB*NC + NB*NM*NC;
    for (int i = blockIdx.x * blockDim.x + threadIdx.x; i < total;
         i += gridDim.x * blockDim.x) {
        if (i < NB*NM)            g_Ksum[i] = 0.f;
        else if (i < NB*NM+NB*NC) g_vsum[i - NB*NM] = 0.f;
        else                      g_matrix[i - NB*NM - NB*NC] = 0.f;
    }
}

// ---------------- GEMM1: QKV = [Wq;Wk;Wv] @ x + bias ----------------
// grid (NPIX/128, 4, NB), 256 threads, BM=BN=128, BK=16, 8x8 micro-tile
__global__ __launch_bounds__(256) void gemm_qkv(
    const float* __restrict__ x,
    const float* __restrict__ Wq, const float* __restrict__ bq,
    const float* __restrict__ Wk, const float* __restrict__ bk,
    const float* __restrict__ Wv, const float* __restrict__ bv)
{
    const int b  = blockIdx.z;
    const int mt = blockIdx.y;     // 0:Q 1:K 2,3:V halves
    const int nt = blockIdx.x;

    const float *W, *bias; int wrow0;
    if (mt == 0)      { W = Wq; bias = bq; wrow0 = 0; }
    else if (mt == 1) { W = Wk; bias = bk; wrow0 = 0; }
    else              { W = Wv; bias = bv; wrow0 = (mt - 2) * 128; }

    __shared__ float As[16][129];   // [k][row], pad 1 -> conflict-free store
    __shared__ float Bs[16][128];   // [k][n], float4 reads

    const int tid = threadIdx.x;
    const int tx = tid & 15, ty = tid >> 4;
    const float* xb = x + (size_t)b * NC * NPIX + (size_t)nt * 128;

    float acc[8][8] = {};

    for (int kt = 0; kt < NC / 16; ++kt) {
        #pragma unroll
        for (int s = 0; s < 8; s++) {            // A tile 128x16
            int idx = tid + s * 256;
            int r = idx >> 4, k = idx & 15;
            As[k][r] = W[(size_t)(wrow0 + r) * NC + kt * 16 + k];
        }
        #pragma unroll
        for (int s = 0; s < 8; s++) {            // B tile 16x128
            int idx = tid + s * 256;
            int k = idx >> 7, n = idx & 127;
            Bs[k][n] = xb[(size_t)(kt * 16 + k) * NPIX + n];
        }
        __syncthreads();
        #pragma unroll
        for (int kk = 0; kk < 16; kk++) {
            float a[8];
            #pragma unroll
            for (int i = 0; i < 8; i++) a[i] = As[kk][ty * 8 + i];
            float4 b0 = *reinterpret_cast<const float4*>(&Bs[kk][tx * 8]);
            float4 b1 = *reinterpret_cast<const float4*>(&Bs[kk][tx * 8 + 4]);
            float bb[8] = {b0.x, b0.y, b0.z, b0.w, b1.x, b1.y, b1.z, b1.w};
            #pragma unroll
            for (int i = 0; i < 8; i++)
                #pragma unroll
                for (int j = 0; j < 8; j++)
                    acc[i][j] = fmaf(a[i], bb[j], acc[i][j]);
        }
        __syncthreads();
    }

    float* out = g_QKV + (size_t)b * 512 * NPIX + (size_t)mt * 128 * NPIX
               + (size_t)nt * 128;
    #pragma unroll
    for (int i = 0; i < 8; i++) {
        float bv_ = bias[wrow0 + ty * 8 + i];
        #pragma unroll
        for (int j = 0; j < 8; j++)
            out[(size_t)(ty * 8 + i) * NPIX + tx * 8 + j] = acc[i][j] + bv_;
    }
}

// ---------------- per-pixel inverse channel norms of Q and K ----------------
__global__ void norms_kernel() {
    const int b = blockIdx.y;
    const int n = blockIdx.x * 256 + threadIdx.x;
    const float* Qb = g_QKV + (size_t)b * 512 * NPIX;
    const float* Kb = Qb + (size_t)128 * NPIX;
    float sq = 0.f, sk = 0.f;
    for (int c = 0; c < NM; c++) {
        float q = Qb[(size_t)c * NPIX + n]; sq = fmaf(q, q, sq);
        float k = Kb[(size_t)c * NPIX + n]; sk = fmaf(k, k, sk);
    }
    g_invQ[b * NPIX + n] = rsqrtf(sq);
    g_invK[b * NPIX + n] = rsqrtf(sk);
}

// ---------------- GEMM2: matrix[m][C] = sum_n Kn[m,n] V[C,n]; + Ksum, vsum ----
// grid (16 splitK, 2 C-halves, NB), 256 thr. Each block reduces 1024 pixels.
__global__ __launch_bounds__(256) void gemm_kv() {
    const int chunk = blockIdx.x, ch = blockIdx.y, b = blockIdx.z;

    __shared__ float Ks[16][132];   // [nloc][m-ch], pad4 keeps float4 alignment unused here, store ~conflict-free
    __shared__ float Vs[16][132];   // [nloc][C-ch], float4 reads aligned (528B rows)
    __shared__ float red[128];

    const int tid = threadIdx.x, tx = tid & 15, ty = tid >> 4;
    const float* Kb = g_QKV + (size_t)b * 512 * NPIX + (size_t)128 * NPIX;
    const float* Vb = g_QKV + (size_t)b * 512 * NPIX + (size_t)256 * NPIX
                    + (size_t)ch * 128 * NPIX;
    const float* iK = g_invK + b * NPIX;
    const int n0 = chunk * 1024;

    float acc[8][8] = {};
    float ksacc[8] = {}, vsacc[8] = {};
    const int nl = tid & 15;

    for (int it = 0; it < 64; ++it) {
        const int nb_ = n0 + it * 16;
        const float ik = iK[nb_ + nl];
        #pragma unroll
        for (int s = 0; s < 8; s++) {
            int idx = tid + s * 256;
            int c = idx >> 4;                 // = 16*s + ty  (fixed per s)
            float kv = Kb[(size_t)c * NPIX + nb_ + nl] * ik;
            Ks[nl][c] = kv;  ksacc[s] += kv;
            float vv = Vb[(size_t)c * NPIX + nb_ + nl];
            Vs[nl][c] = vv;  vsacc[s] += vv;
        }
        __syncthreads();
        #pragma unroll
        for (int kk = 0; kk < 16; kk++) {
            float a[8];
            #pragma unroll
            for (int i = 0; i < 8; i++) a[i] = Ks[kk][ty * 8 + i];
            float4 b0 = *reinterpret_cast<const float4*>(&Vs[kk][tx * 8]);
            float4 b1 = *reinterpret_cast<const float4*>(&Vs[kk][tx * 8 + 4]);
            float bb[8] = {b0.x, b0.y, b0.z, b0.w, b1.x, b1.y, b1.z, b1.w};
            #pragma unroll
            for (int i = 0; i < 8; i++)
                #pragma unroll
                for (int j = 0; j < 8; j++)
                    acc[i][j] = fmaf(a[i], bb[j], acc[i][j]);
        }
        __syncthreads();
    }

    // matrix partial -> global atomics
    float* mb = g_matrix + (size_t)b * NM * NC + ch * 128;
    #pragma unroll
    for (int i = 0; i < 8; i++)
        #pragma unroll
        for (int j = 0; j < 8; j++)
            atomicAdd(&mb[(size_t)(ty * 8 + i) * NC + tx * 8 + j], acc[i][j]);

    // vsum (this block's C half)
    if (tid < 128) red[tid] = 0.f;
    __syncthreads();
    #pragma unroll
    for (int s = 0; s < 8; s++) atomicAdd(&red[ty + s * 16], vsacc[s]);
    __syncthreads();
    if (tid < 128) atomicAdd(&g_vsum[b * NC + ch * 128 + tid], red[tid]);
    __syncthreads();

    // Ksum (only C-half 0 blocks, K is shared between halves)
    if (ch == 0) {
        if (tid < 128) red[tid] = 0.f;
        __syncthreads();
        #pragma unroll
        for (int s = 0; s < 8; s++) atomicAdd(&red[ty + s * 16], ksacc[s]);
        __syncthreads();
        if (tid < 128) atomicAdd(&g_Ksum[b * NM + tid], red[tid]);
    }
}

// ---------------- tailor[n] = 1/(N + Qn . (Ksum + eps)) ----------------
__global__ void tailor_kernel() {
    __shared__ float ks[128];
    const int b = blockIdx.y;
    const int n = blockIdx.x * 256 + threadIdx.x;
    if (threadIdx.x < 128) ks[threadIdx.x] = g_Ksum[b * NM + threadIdx.x] + EPSV;
    __syncthreads();
    const float* Qb = g_QKV + (size_t)b * 512 * NPIX;
    float dot = 0.f;
    for (int c = 0; c < NM; c++)
        dot = fmaf(Qb[(size_t)c * NPIX + n], ks[c], dot);
    g_tailor[b * NPIX + n] =
        1.0f / ((float)NPIX + g_invQ[b * NPIX + n] * dot);
}

// ---------------- GEMM3: out[c,n] = g*tailor[n]*(vsum[c] + sum_m matrix[m][c]*Qn[m,n]) --
// grid (NPIX/128, 2, NB), 256 thr, K = 128 (m), BK=16
__global__ __launch_bounds__(256) void gemm_out(
    const float* __restrict__ gamma, float* __restrict__ out)
{
    const int nt = blockIdx.x, ch = blockIdx.y, b = blockIdx.z;

    __shared__ float As[16][128];   // [mloc][c]
    __shared__ float Bs[16][128];   // [mloc][n]

    const int tid = threadIdx.x, tx = tid & 15, ty = tid >> 4;
    const float* Qb  = g_QKV + (size_t)b * 512 * NPIX + (size_t)nt * 128;
    const float* iQ  = g_invQ + b * NPIX + nt * 128;
    const float* mat = g_matrix + (size_t)b * NM * NC + ch * 128;

    float acc[8][8] = {};

    for (int mt = 0; mt < 8; ++mt) {
        #pragma unroll
        for (int s = 0; s < 8; s++) {
            int idx = tid + s * 256;
            int ml = idx >> 7, c = idx & 127;
            As[ml][c] = mat[(size_t)(mt * 16 + ml) * NC + c];
            Bs[ml][c] = Qb[(size_t)(mt * 16 + ml) * NPIX + c] * iQ[c];
        }
        __syncthreads();
        #pragma unroll
        for (int kk = 0; kk < 16; kk++) {
            float a[8];
            #pragma unroll
            for (int i = 0; i < 8; i++) a[i] = As[kk][ty * 8 + i];
            float4 b0 = *reinterpret_cast<const float4*>(&Bs[kk][tx * 8]);
            float4 b1 = *reinterpret_cast<const float4*>(&Bs[kk][tx * 8 + 4]);
            float bb[8] = {b0.x, b0.y, b0.z, b0.w, b1.x, b1.y, b1.z, b1.w};
            #pragma unroll
            for (int i = 0; i < 8; i++)
                #pragma unroll
                for (int j = 0; j < 8; j++)
                    acc[i][j] = fmaf(a[i], bb[j], acc[i][j]);
        }
        __syncthreads();
    }

    const float g = gamma[0];
    float tl[8];
    #pragma unroll
    for (int j = 0; j < 8; j++)
        tl[j] = g * g_tailor[b * NPIX + nt * 128 + tx * 8 + j];

    float* ob = out + (size_t)b * NC * NPIX + (size_t)ch * 128 * NPIX
              + (size_t)nt * 128;
    #pragma unroll
    for (int i = 0; i < 8; i++) {
        float vs = g_vsum[b * NC + ch * 128 + ty * 8 + i];
        #pragma unroll
        for (int j = 0; j < 8; j++)
            ob[(size_t)(ty * 8 + i) * NPIX + tx * 8 + j] =
                tl[j] * (vs + acc[i][j]);
    }
}

// ---------------- launch ----------------
extern "C" void kernel_launch(void* const* d_in, const int* in_sizes, int n_in,
                              void* d_out, int out_size)
{
    const float* x     = (const float*)d_in[0];
    const float* Wq    = (const float*)d_in[1];
    const float* bq    = (const float*)d_in[2];
    const float* Wk    = (const float*)d_in[3];
    const float* bk    = (const float*)d_in[4];
    const float* Wv    = (const float*)d_in[5];
    const float* bv    = (const float*)d_in[6];
    const float* gamma = (const float*)d_in[7];
    float* out = (float*)d_out;

    zero_kernel<<<64, 256>>>();
    gemm_qkv<<<dim3(NPIX / 128, 4, NB), 256>>>(x, Wq, bq, Wk, bk, Wv, bv);
    norms_kernel<<<dim3(NPIX / 256, NB), 256>>>();
    gemm_kv<<<dim3(16, 2, NB), 256>>>();
    tailor_kernel<<<dim3(NPIX / 256, NB), 256>>>();
    gemm_out<<<dim3(NPIX / 128, 2, NB), 256>>>(gamma, out);
}